// round 4
// baseline (speedup 1.0000x reference)
#include <cuda_runtime.h>
#include <cstdint>

// Problem constants
#define BB 8
#define NN 2048
#define DD 128
#define HH 4
#define DH 32
#define NBH 32          // B*H
#define BN 16384        // B*N

// ---------------- device scratch ----------------
__device__ float g_h[NBH * NN * DH];          // (b,h,n,dh) = 2M floats
__device__ float g_src[NBH * NN];
__device__ float g_dst[NBH * NN];
__device__ float g_E [NBH * NN];              // exp(src)
__device__ float g_E5[NBH * NN];              // exp(0.2*src)
__device__ float g_F [NBH * NN];              // exp(dst)
__device__ float g_F5[NBH * NN];              // exp(0.2*dst)
__device__ float g_att[BN * DD];              // attention output, (b,n,d)

// packed fp32x2 FMA: c += {a0,a1} * {b,b}
__device__ __forceinline__ void ffma2(float2 &c, float a0, float a1, float b) {
    asm("{\n\t"
        ".reg .b64 ra, rb, rc;\n\t"
        "mov.b64 ra, {%2, %3};\n\t"
        "mov.b64 rb, {%4, %4};\n\t"
        "mov.b64 rc, {%0, %1};\n\t"
        "fma.rn.f32x2 rc, ra, rb, rc;\n\t"
        "mov.b64 {%0, %1}, rc;\n\t"
        "}"
        : "+f"(c.x), "+f"(c.y)
        : "f"(a0), "f"(a1), "f"(b));
}

// ---------------- Kernel 1: h = x @ W^T, stored (b,h,n,dh) ----------------
// grid 1024, block 128. Each block: 16 rows (b,n), each thread one output col.
__global__ __launch_bounds__(128) void k1_proj(const float* __restrict__ x,
                                               const float* __restrict__ W) {
    __shared__ float sxt[128][18];     // [k][row], padded
    __shared__ float sW[32][129];      // [k][d'], padded

    const int t = threadIdx.x;
    const int row0 = blockIdx.x * 16;
    const float* xb = x + (size_t)row0 * DD;

    #pragma unroll
    for (int m = 0; m < 16; ++m) sxt[t][m] = xb[m * DD + t];   // coalesced

    float2 acc[8];
    #pragma unroll
    for (int rp = 0; rp < 8; ++rp) acc[rp] = make_float2(0.f, 0.f);

    for (int kt = 0; kt < DD; kt += 32) {
        __syncthreads();
        // stage W[d'][kt..kt+31] -> sW[k][d']
        #pragma unroll
        for (int m = 0; m < 32; ++m) {
            int lin = t + 128 * m;            // 0..4095
            int dp = lin >> 5, k = lin & 31;
            sW[k][dp] = W[dp * DD + kt + k];
        }
        __syncthreads();
        #pragma unroll
        for (int k = 0; k < 32; ++k) {
            float wv = sW[k][t];
            int kk = kt + k;
            #pragma unroll
            for (int rp = 0; rp < 8; ++rp) {
                float2 xp = *(const float2*)&sxt[kk][2 * rp];  // broadcast
                ffma2(acc[rp], xp.x, xp.y, wv);
            }
        }
    }

    const int hh = t >> 5, dh = t & 31;
    #pragma unroll
    for (int rp = 0; rp < 8; ++rp) {
        int bn = row0 + 2 * rp;
        int b = bn >> 11, n = bn & 2047;
        size_t base = (((size_t)b * HH + hh) * NN + n) * DH + dh;
        g_h[base]      = acc[rp].x;
        g_h[base + DH] = acc[rp].y;   // n+1, same b (16-row blocks aligned)
    }
}

// ---------------- Kernel 2: src/dst dots + exps ----------------
__global__ __launch_bounds__(256) void k2_srcdst(const float* __restrict__ a_src,
                                                 const float* __restrict__ a_dst) {
    int idx = blockIdx.x * 256 + threadIdx.x;   // = bh*N + n, < 65536
    int hh = (idx >> 11) & 3;
    const float* hrow = g_h + (size_t)idx * DH;
    const float* as = a_src + hh * DH;
    const float* ad = a_dst + hh * DH;
    float s = 0.f, d = 0.f;
    #pragma unroll
    for (int k = 0; k < DH; ++k) {
        float hv = hrow[k];
        s += hv * as[k];
        d += hv * ad[k];
    }
    g_src[idx] = s;
    g_dst[idx] = d;
    g_E [idx] = __expf(s);
    g_E5[idx] = __expf(0.2f * s);
    g_F [idx] = __expf(d);
    g_F5[idx] = __expf(0.2f * d);
}

// ---------------- Kernel 3: fused attention (the big one) ----------------
// grid (N/64, B*H), block 256 (8 warps). Warp w owns rows i0+8w..i0+8w+7.
// Each lane owns dh = lane; rows packed in pairs via f32x2.
#define TJ 64
__global__ __launch_bounds__(256) void k3_attn(const float* __restrict__ adj) {
    __shared__ float sh_h[TJ * DH];                      // 8 KB
    __shared__ float sh_dst[TJ], sh_F[TJ], sh_F5[TJ];
    __shared__ float sh_adj[64 * TJ];                    // 16 KB
    __shared__ __align__(16) float2 sh_w[8][TJ][4];      // 16 KB

    const int bh = blockIdx.y;
    const int i0 = blockIdx.x * 64;
    const int tid = threadIdx.x;
    const int warp = tid >> 5, lane = tid & 31;
    const int rbase = warp * 8;                // block-local first row of this warp

    // per-row constants (uniform per warp)
    float rs[8], rE[8], rE5[8];
    {
        int gb = bh * NN + i0 + rbase;
        #pragma unroll
        for (int r = 0; r < 8; ++r) {
            rs[r]  = g_src[gb + r];
            rE[r]  = g_E [gb + r];
            rE5[r] = g_E5[gb + r];
        }
    }

    float2 acc[4];
    #pragma unroll
    for (int rp = 0; rp < 4; ++rp) acc[rp] = make_float2(0.f, 0.f);
    float ls[8];
    #pragma unroll
    for (int r = 0; r < 8; ++r) ls[r] = 0.f;

    const float* hbh = g_h + (size_t)bh * NN * DH;
    const int jo = bh * NN;

    for (int jt = 0; jt < NN; jt += TJ) {
        __syncthreads();
        // --- stage tiles ---
        {
            const float4* hsrc = (const float4*)(hbh + (size_t)jt * DH);
            float4* hdst = (float4*)sh_h;
            hdst[tid]       = hsrc[tid];
            hdst[tid + 256] = hsrc[tid + 256];
        }
        if (tid < TJ) {
            int jj = jo + jt + tid;
            sh_dst[tid] = g_dst[jj];
            sh_F [tid] = g_F [jj];
            sh_F5[tid] = g_F5[jj];
        }
        #pragma unroll
        for (int q = 0; q < 4; ++q) {
            int lin = tid + 256 * q;           // < 1024 float4s
            int rl = lin >> 4, c4 = lin & 15;
            *(float4*)(sh_adj + rl * TJ + c4 * 4) =
                *(const float4*)(adj + (size_t)(i0 + rl) * NN + jt + c4 * 4);
        }
        __syncthreads();

        // --- phase A: compute weights w(i,j), vectorized over j ---
        #pragma unroll
        for (int jb = 0; jb < TJ; jb += 32) {
            int j = jb + lane;
            float dv  = sh_dst[j];
            float Fv  = sh_F[j];
            float F5v = sh_F5[j];
            #pragma unroll
            for (int rp = 0; rp < 4; ++rp) {
                int r0 = 2 * rp, r1 = r0 + 1;
                float s0 = rs[r0] + dv;
                float c0 = (s0 > 0.f) ? rE[r0] * Fv : rE5[r0] * F5v;
                float w0 = c0 * sh_adj[(rbase + r0) * TJ + j];
                float s1 = rs[r1] + dv;
                float c1 = (s1 > 0.f) ? rE[r1] * Fv : rE5[r1] * F5v;
                float w1 = c1 * sh_adj[(rbase + r1) * TJ + j];
                ls[r0] += w0;
                ls[r1] += w1;
                sh_w[warp][j][rp] = make_float2(w0, w1);
            }
        }
        __syncwarp();

        // --- phase B: acc += w * h, packed pairs of rows ---
        const float4* wq = (const float4*)&sh_w[warp][0][0];
        #pragma unroll 8
        for (int j = 0; j < TJ; ++j) {
            float hv = sh_h[j * DH + lane];    // distinct banks, no conflict
            float4 wa = wq[j * 2];             // broadcast
            float4 wb = wq[j * 2 + 1];         // broadcast
            ffma2(acc[0], wa.x, wa.y, hv);
            ffma2(acc[1], wa.z, wa.w, hv);
            ffma2(acc[2], wb.x, wb.y, hv);
            ffma2(acc[3], wb.z, wb.w, hv);
        }
    }

    // --- epilogue: reduce row sums over lanes, normalize, write ---
    float rinv[8];
    #pragma unroll
    for (int r = 0; r < 8; ++r) {
        float v = ls[r];
        #pragma unroll
        for (int off = 16; off > 0; off >>= 1)
            v += __shfl_xor_sync(0xffffffffu, v, off);
        rinv[r] = 1.0f / v;
    }

    const int b = bh >> 2, hh = bh & 3;
    #pragma unroll
    for (int rp = 0; rp < 4; ++rp) {
        int r0 = 2 * rp;
        int i_a = i0 + rbase + r0;
        int i_b = i_a + 1;
        g_att[((size_t)b * NN + i_a) * DD + hh * DH + lane] = acc[rp].x * rinv[r0];
        g_att[((size_t)b * NN + i_b) * DD + hh * DH + lane] = acc[rp].y * rinv[r0 + 1];
    }
}

// ---------------- Kernel 4: out = att @ Wo^T + bo; y = x + out; LayerNorm ----
// grid 1024, block 128, 16 rows per block (same GEMM structure as k1).
__global__ __launch_bounds__(128) void k4_proj_ln(const float* __restrict__ x,
                                                  const float* __restrict__ Wo,
                                                  const float* __restrict__ bo,
                                                  const float* __restrict__ gamma,
                                                  const float* __restrict__ beta,
                                                  float* __restrict__ out) {
    __shared__ float sat[128][18];
    __shared__ float sW[32][129];
    __shared__ float sy[16][128];
    __shared__ float smu[16], srstd[16];

    const int t = threadIdx.x;
    const int row0 = blockIdx.x * 16;
    const float* ab = g_att + (size_t)row0 * DD;

    #pragma unroll
    for (int m = 0; m < 16; ++m) sat[t][m] = ab[m * DD + t];

    float2 acc[8];
    #pragma unroll
    for (int rp = 0; rp < 8; ++rp) acc[rp] = make_float2(0.f, 0.f);

    for (int kt = 0; kt < DD; kt += 32) {
        __syncthreads();
        #pragma unroll
        for (int m = 0; m < 32; ++m) {
            int lin = t + 128 * m;
            int dp = lin >> 5, k = lin & 31;
            sW[k][dp] = Wo[dp * DD + kt + k];
        }
        __syncthreads();
        #pragma unroll
        for (int k = 0; k < 32; ++k) {
            float wv = sW[k][t];
            int kk = kt + k;
            #pragma unroll
            for (int rp = 0; rp < 8; ++rp) {
                float2 xp = *(const float2*)&sat[kk][2 * rp];
                ffma2(acc[rp], xp.x, xp.y, wv);
            }
        }
    }
    __syncthreads();

    // y = x + o + bo, stash to smem + regs
    const float bov = bo[t];
    float yv[16];
    #pragma unroll
    for (int rp = 0; rp < 8; ++rp) {
        int r0 = 2 * rp;
        float y0 = x[(size_t)(row0 + r0) * DD + t]     + acc[rp].x + bov;
        float y1 = x[(size_t)(row0 + r0 + 1) * DD + t] + acc[rp].y + bov;
        yv[r0] = y0; yv[r0 + 1] = y1;
        sy[r0][t] = y0; sy[r0 + 1][t] = y1;
    }
    __syncthreads();

    // per-row mean/var: warp w handles rows 4w..4w+3
    {
        int w = t >> 5, lane = t & 31;
        #pragma unroll
        for (int rr = 0; rr < 4; ++rr) {
            int r = w * 4 + rr;
            float s = 0.f, q = 0.f;
            #pragma unroll
            for (int c = 0; c < 4; ++c) {
                float v = sy[r][lane + 32 * c];
                s += v;
                q += v * v;
            }
            #pragma unroll
            for (int off = 16; off > 0; off >>= 1) {
                s += __shfl_xor_sync(0xffffffffu, s, off);
                q += __shfl_xor_sync(0xffffffffu, q, off);
            }
            if (lane == 0) {
                float mu = s * (1.0f / DD);
                float var = q * (1.0f / DD) - mu * mu;
                smu[r] = mu;
                srstd[r] = rsqrtf(var + 1e-5f);
            }
        }
    }
    __syncthreads();

    const float gv = gamma[t], bev = beta[t];
    #pragma unroll
    for (int r = 0; r < 16; ++r) {
        out[(size_t)(row0 + r) * DD + t] = (yv[r] - smu[r]) * srstd[r] * gv + bev;
    }
}

// ---------------- launch ----------------
extern "C" void kernel_launch(void* const* d_in, const int* in_sizes, int n_in,
                              void* d_out, int out_size) {
    const float* x     = (const float*)d_in[0];
    const float* adj   = (const float*)d_in[1];
    const float* W     = (const float*)d_in[2];
    const float* a_src = (const float*)d_in[3];
    const float* a_dst = (const float*)d_in[4];
    const float* Wo    = (const float*)d_in[5];
    const float* bo    = (const float*)d_in[6];
    const float* gamma = (const float*)d_in[7];
    const float* beta  = (const float*)d_in[8];
    float* out = (float*)d_out;

    k1_proj<<<BN / 16, 128>>>(x, W);
    k2_srcdst<<<(NBH * NN) / 256, 256>>>(a_src, a_dst);
    k3_attn<<<dim3(NN / 64, NBH), 256>>>(adj);
    k4_proj_ln<<<BN / 16, 128>>>(x, Wo, bo, gamma, beta, out);
}